// round 12
// baseline (speedup 1.0000x reference)
#include <cuda_runtime.h>
#include <cuda_bf16.h>
#include <stdint.h>
#include <math.h>

#define Bn 128
#define Ln 1024
#define Vn 32
#define En 256
#define Hn 1024
#define NTOT 1056        // Hn + Vn (W_o folded)

#define NG  4            // independent batch groups
#define BG  32           // batch rows per group
#define NTL 33           // CTAs per group (32 h-tiles + 1 logits tile)
#define NSL 32           // N cols per CTA
#define G   (NG * NTL)   // 132 persistent CTAs
#define NT  256          // 8 warps (one per k-slice)
#define KW  128          // K columns per warp
#define PA  1032         // A/B smem pitch (bf16): 2064B stride -> LDSM conflict-free
#define PN  36           // reduction pitch (floats)

// ---------------- device scratch ----------------
__device__ float         g_P[Vn * Hn];
__device__ __nv_bfloat16 g_hbf_hi[2][Bn * Hn];
__device__ __nv_bfloat16 g_hbf_lo[2][Bn * Hn];
__device__ __nv_bfloat16 g_WT_hi[NTOT * Hn];   // [n][k]
__device__ __nv_bfloat16 g_WT_lo[NTOT * Hn];
__device__ unsigned      g_cnt_all;            // prologue barrier (all G)
__device__ unsigned      g_cntg[NG * 8];       // per-group step counters (padded)

// smem layout (bytes)
#define OFF_ALO 66048                          // 32*PA*2
#define OFF_RED 132096
#define OFF_X   168960
#define SMEM_BYTES 169088
#define A_MT (16 * PA * 2)                     // byte offset between m-tiles

// ---------------- helpers ----------------
#define MMA16816(d, a0, a1, a2, a3, b0, b1) \
    asm volatile("mma.sync.aligned.m16n8k16.row.col.f32.bf16.bf16.f32 " \
        "{%0,%1,%2,%3}, {%4,%5,%6,%7}, {%8,%9}, {%0,%1,%2,%3};" \
        : "+f"((d)[0]), "+f"((d)[1]), "+f"((d)[2]), "+f"((d)[3]) \
        : "r"(a0), "r"(a1), "r"(a2), "r"(a3), "r"(b0), "r"(b1))

#define LDSM4(r0, r1, r2, r3, addr) \
    asm volatile("ldmatrix.sync.aligned.m8n8.x4.shared.b16 {%0,%1,%2,%3}, [%4];" \
        : "=r"(r0), "=r"(r1), "=r"(r2), "=r"(r3) : "r"(addr))

#define CPASYNC16(saddr, gptr) \
    asm volatile("cp.async.cg.shared.global [%0], [%1], 16;" \
        :: "r"((uint32_t)(saddr)), "l"(gptr))
#define CPCOMMIT() asm volatile("cp.async.commit_group;" ::: "memory")
#define CPWAIT(n)  asm volatile("cp.async.wait_group %0;" :: "n"(n) : "memory")

__device__ __forceinline__ uint32_t smem_u32(const void* p) {
    uint32_t a;
    asm("{ .reg .u64 t; cvta.to.shared.u64 t, %1; cvt.u32.u64 %0, t; }"
        : "=r"(a) : "l"(p));
    return a;
}
__device__ __forceinline__ unsigned acqload(const unsigned* p) {
    unsigned v;
    asm volatile("ld.acquire.gpu.u32 %0, [%1];" : "=r"(v) : "l"(p) : "memory");
    return v;
}
__device__ __forceinline__ void arrive(unsigned* cnt) {
    asm volatile("red.release.gpu.global.add.u32 [%0], 1;" :: "l"(cnt) : "memory");
}
__device__ __forceinline__ void waitcnt(unsigned* cnt, unsigned target) {
    unsigned v = acqload(cnt);
    while ((int)(v - target) < 0) v = acqload(cnt);
}
__device__ __forceinline__ void pack_hilo(float v, unsigned short& hi, unsigned short& lo) {
    __nv_bfloat16 hb = __float2bfloat16(v);
    hi = __bfloat16_as_ushort(hb);
    lo = __bfloat16_as_ushort(__float2bfloat16(v - __bfloat162float(hb)));
}
__device__ __forceinline__ float fast_tanh(float x) {
    float e = __expf(2.0f * x);
    return 1.0f - __fdividef(2.0f, e + 1.0f);
}

// ---------------- the single persistent kernel ----------------
__global__ void __launch_bounds__(NT, 1)
rnn_all(const int* __restrict__ x, const float* __restrict__ hidden,
        const float* __restrict__ emb, const float* __restrict__ We,
        const float* __restrict__ Wh, const float* __restrict__ bh,
        const float* __restrict__ Wo, const float* __restrict__ bo,
        float* __restrict__ logits, float* __restrict__ outh) {
    extern __shared__ __align__(16) char dsm[];
    __nv_bfloat16* sAhi = (__nv_bfloat16*)dsm;
    __nv_bfloat16* sAlo = (__nv_bfloat16*)(dsm + OFF_ALO);
    float*         sRed = (float*)(dsm + OFF_RED);
    int*           sX   = (int*)(dsm + OFF_X);

    const int tid = threadIdx.x, bid = blockIdx.x;
    const int g     = bid / NTL;        // batch group 0..3
    const int ntl   = bid % NTL;        // 0..32 (32 = logits tile)
    const int gbase = g * BG;
    const int ncol0 = ntl * NSL;        // global N col base (1024 = logits)
    const int lane = tid & 31, w = tid >> 5;
    const int gq = lane >> 2, tg = lane & 3;
    const int kw = w * KW;              // this warp's k-slice base

    unsigned tokA = acqload(&g_cnt_all);
    unsigned tokG = acqload(&g_cntg[g * 8]);

    // ======== prologue ========
    for (int k2 = tid; k2 < Hn; k2 += NT) {
#pragma unroll
        for (int j = 0; j < 8; ++j) {
            int n = bid * 8 + j;
            float wv = (n < Hn) ? Wh[k2 * Hn + n] : Wo[k2 * Vn + (n - Hn)];
            unsigned short hi, lo; pack_hilo(wv, hi, lo);
            g_WT_hi[n * Hn + k2] = __ushort_as_bfloat16(hi);
            g_WT_lo[n * Hn + k2] = __ushort_as_bfloat16(lo);
        }
    }
    {
        int e = bid * NT + tid;
        if (e < Vn * Hn) {
            int v = e >> 10, h = e & 1023;
            float acc = bh[h];
            const float* er = emb + v * En;
#pragma unroll 8
            for (int q = 0; q < En; ++q) acc = fmaf(er[q], We[q * Hn + h], acc);
            g_P[e] = acc;
        }
    }
    if (bid < Bn) {
        int i0 = bid * Hn + tid * 4;
        float4 hv = *(const float4*)(hidden + i0);
        float vv[4] = {hv.x, hv.y, hv.z, hv.w};
        unsigned short uh[4], ul[4];
#pragma unroll
        for (int j = 0; j < 4; ++j) pack_hilo(vv[j], uh[j], ul[j]);
        *(uint2*)(&g_hbf_hi[0][i0]) = make_uint2(uh[0] | (uh[1] << 16), uh[2] | (uh[3] << 16));
        *(uint2*)(&g_hbf_lo[0][i0]) = make_uint2(ul[0] | (ul[1] << 16), ul[2] | (ul[3] << 16));
    }
    __syncthreads();
    if (tid == 0) arrive(&g_cnt_all);
    tokA += G;
    if (tid == 0) waitcnt(&g_cnt_all, tokA);
    __syncthreads();

    // ======== B setup: stage tile once, LDSM fragments into registers ========
    uint32_t Bh[8][4][2], Bl[8][4][2];
    {
#pragma unroll
        for (int it = 0; it < 16; ++it) {
            int i = (it * NT + tid) * 8;
            int n = i >> 10, k = i & 1023;
            *(uint4*)(sAhi + n * PA + k) = *(const uint4*)(&g_WT_hi[(ncol0 + n) * Hn + k]);
            *(uint4*)(sAlo + n * PA + k) = *(const uint4*)(&g_WT_lo[(ncol0 + n) * Hn + k]);
        }
        __syncthreads();
        const uint32_t bBase = smem_u32(sAhi) +
            (uint32_t)(2 * ((lane & 7) * PA + kw + ((lane >> 3) & 1) * 8));
#pragma unroll
        for (int nb2 = 0; nb2 < 2; ++nb2) {
            const uint32_t ba = bBase + (uint32_t)(2 * (nb2 * 2 + (lane >> 4)) * 8 * PA);
#pragma unroll
            for (int ks = 0; ks < 8; ++ks) {
                LDSM4(Bh[ks][nb2 * 2][0], Bh[ks][nb2 * 2][1],
                      Bh[ks][nb2 * 2 + 1][0], Bh[ks][nb2 * 2 + 1][1], ba + ks * 32);
                LDSM4(Bl[ks][nb2 * 2][0], Bl[ks][nb2 * 2][1],
                      Bl[ks][nb2 * 2 + 1][0], Bl[ks][nb2 * 2 + 1][1],
                      ba + ks * 32 + (uint32_t)OFF_ALO);
            }
        }
        __syncthreads();
    }

    // A fragment base (this warp's k-slice) + smem staging bases
    const uint32_t aHiAddr = smem_u32(sAhi) +
        (uint32_t)(2 * (((lane & 7) + ((lane >> 3) & 1) * 8) * PA + kw + (lane >> 4) * 8));
    const uint32_t aLoAddr = aHiAddr + (uint32_t)OFF_ALO;
    const uint32_t sAhiU = smem_u32(sAhi);

    // ======== recurrence ========
    for (int l = 0; l <= Ln; ++l) {
        const int c = l & 1;
        const bool act = (l < Ln) || (ntl == NTL - 1);

        if (act) {   // stage A via cp.async: hi group then lo group
#pragma unroll
            for (int it = 0; it < 16; ++it) {
                int i = (it * NT + tid) * 8;
                int row = i >> 10, k = i & 1023;
                CPASYNC16(sAhiU + (uint32_t)(2 * (row * PA + k)),
                          &g_hbf_hi[c][(gbase + row) * Hn + k]);
            }
            CPCOMMIT();
#pragma unroll
            for (int it = 0; it < 16; ++it) {
                int i = (it * NT + tid) * 8;
                int row = i >> 10, k = i & 1023;
                CPASYNC16(sAhiU + (uint32_t)OFF_ALO + (uint32_t)(2 * (row * PA + k)),
                          &g_hbf_lo[c][(gbase + row) * Hn + k]);
            }
            CPCOMMIT();
        } else {
            CPCOMMIT(); CPCOMMIT();   // keep group counts uniform
        }
        if (l < Ln && tid < BG) sX[tid] = __ldg(&x[(gbase + tid) * Ln + l]);
        CPWAIT(1);                     // hi group landed; lo still in flight
        __syncthreads();

        float acc[2][4][4];
#pragma unroll
        for (int mt = 0; mt < 2; ++mt)
#pragma unroll
            for (int nb = 0; nb < 4; ++nb)
#pragma unroll
                for (int q = 0; q < 4; ++q) acc[mt][nb][q] = 0.f;

        if (act) {
            // ---- hi phase: Ahi*Bhi + Ahi*Blo (lo copies drain underneath) ----
#pragma unroll
            for (int mt = 0; mt < 2; ++mt) {
                const uint32_t mo = (uint32_t)(mt * A_MT);
#pragma unroll
                for (int ks = 0; ks < 8; ++ks) {
                    uint32_t a0, a1, a2, a3;
                    LDSM4(a0, a1, a2, a3, aHiAddr + mo + ks * 32);
#pragma unroll
                    for (int nb = 0; nb < 4; ++nb) {
                        MMA16816(acc[mt][nb], a0, a1, a2, a3, Bh[ks][nb][0], Bh[ks][nb][1]);
                        MMA16816(acc[mt][nb], a0, a1, a2, a3, Bl[ks][nb][0], Bl[ks][nb][1]);
                    }
                }
            }
        }
        CPWAIT(0);
        __syncthreads();

        if (act) {
            // ---- lo phase: Alo*Bhi ----
#pragma unroll
            for (int mt = 0; mt < 2; ++mt) {
                const uint32_t mo = (uint32_t)(mt * A_MT);
#pragma unroll
                for (int ks = 0; ks < 8; ++ks) {
                    uint32_t a0, a1, a2, a3;
                    LDSM4(a0, a1, a2, a3, aLoAddr + mo + ks * 32);
#pragma unroll
                    for (int nb = 0; nb < 4; ++nb)
                        MMA16816(acc[mt][nb], a0, a1, a2, a3, Bh[ks][nb][0], Bh[ks][nb][1]);
                }
            }
            // store per-warp partials (k-slice sums) to smem
            float* rp = sRed + w * 32 * PN;
#pragma unroll
            for (int mt = 0; mt < 2; ++mt)
#pragma unroll
                for (int nb = 0; nb < 4; ++nb) {
                    int r0 = mt * 16 + gq, col = nb * 8 + tg * 2;
                    *(float2*)(rp + r0 * PN + col)       = make_float2(acc[mt][nb][0], acc[mt][nb][1]);
                    *(float2*)(rp + (r0 + 8) * PN + col) = make_float2(acc[mt][nb][2], acc[mt][nb][3]);
                }
        }
        __syncthreads();

        if (act) {
            // reduce 8 k-slices: thread owns row m, cols n0..n0+3
            const int m = tid >> 3, n0 = (tid & 7) * 4;
            float4 s = *(const float4*)(sRed + m * PN + n0);
#pragma unroll
            for (int j = 1; j < 8; ++j) {
                float4 p = *(const float4*)(sRed + j * 32 * PN + m * PN + n0);
                s.x += p.x; s.y += p.y; s.z += p.z; s.w += p.w;
            }
            if (ntl < NTL - 1) {
                if (l < Ln) {
                    const int xv = sX[m];
                    float4 Pv = *(const float4*)(&g_P[xv * Hn + ncol0 + n0]);
                    float h0 = fast_tanh(s.x + Pv.x), h1 = fast_tanh(s.y + Pv.y);
                    float h2 = fast_tanh(s.z + Pv.z), h3 = fast_tanh(s.w + Pv.w);
                    unsigned short uh[4], ul[4];
                    pack_hilo(h0, uh[0], ul[0]); pack_hilo(h1, uh[1], ul[1]);
                    pack_hilo(h2, uh[2], ul[2]); pack_hilo(h3, uh[3], ul[3]);
                    int i0 = (gbase + m) * Hn + ncol0 + n0;
                    *(uint2*)(&g_hbf_hi[1 - c][i0]) =
                        make_uint2(uh[0] | (uh[1] << 16), uh[2] | (uh[3] << 16));
                    *(uint2*)(&g_hbf_lo[1 - c][i0]) =
                        make_uint2(ul[0] | (ul[1] << 16), ul[2] | (ul[3] << 16));
                    if (l == Ln - 1)
                        *(float4*)(&outh[i0]) = make_float4(h0, h1, h2, h3);
                }
            } else if (l > 0) {
                float4 B0 = *(const float4*)(&bo[n0]);
                *(float4*)(&logits[((size_t)(gbase + m) * Ln + (l - 1)) * Vn + n0]) =
                    make_float4(s.x + B0.x, s.y + B0.y, s.z + B0.z, s.w + B0.w);
            }
        }

        // per-group barrier (1 per step)
        if (l < Ln) {
            __syncthreads();
            if (tid == 0) arrive(&g_cntg[g * 8]);
            tokG += NTL;
            if (tid == 0) waitcnt(&g_cntg[g * 8], tokG);
            __syncthreads();
        }
    }
}

extern "C" void kernel_launch(void* const* d_in, const int* in_sizes, int n_in,
                              void* d_out, int out_size) {
    const int*   x      = (const int*)d_in[0];
    const float* hidden = (const float*)d_in[1];
    const float* emb    = (const float*)d_in[2];
    const float* We     = (const float*)d_in[3];
    const float* Wh     = (const float*)d_in[4];
    const float* bh     = (const float*)d_in[5];
    const float* Wo     = (const float*)d_in[6];
    const float* bo     = (const float*)d_in[7];

    float* logits = (float*)d_out;
    float* outh   = logits + (size_t)Bn * Ln * Vn;

    cudaFuncSetAttribute(rnn_all,
                         cudaFuncAttributeMaxDynamicSharedMemorySize, SMEM_BYTES);
    rnn_all<<<G, NT, SMEM_BYTES>>>(x, hidden, emb, We, Wh, bh, Wo, bo, logits, outh);
}